// round 16
// baseline (speedup 1.0000x reference)
#include <cuda_runtime.h>
#include <cuda_fp16.h>
#include <math.h>
#include <stdint.h>

#define EMB 1024
#define NH  16
#define HD  64
#define BB  4
#define SS  2048
#define MT  (BB*SS)    // 8192 rows
#define NQKV 3072
#define KT16 (EMB/16)  // 64 k16-tiles per 1024

// Scratch (allocation-free rule: __device__ globals)
__device__ __half g_x[(size_t)MT*EMB];
__device__ __half g_qkv[(size_t)MT*NQKV];
__device__ __half g_o[(size_t)MT*EMB];
__device__ __half g_wqkv[(size_t)NQKV*EMB];
__device__ float  g_bqkv[NQKV];
__device__ __half g_wo[(size_t)EMB*EMB];

#define LOG2E 1.44269504088896f

__device__ __forceinline__ uint32_t h2u(float lo, float hi) {
    __half2 h = __floats2half2_rn(lo, hi);
    return *(uint32_t*)&h;
}
__device__ __forceinline__ uint32_t ex2h2(uint32_t x) {
    uint32_t r;
    asm("ex2.approx.f16x2 %0, %1;" : "=r"(r) : "r"(x));
    return r;
}

__device__ __forceinline__ void mma_f16(
    float& c0, float& c1, float& c2, float& c3,
    uint32_t a0, uint32_t a1, uint32_t a2, uint32_t a3,
    uint32_t b0, uint32_t b1)
{
    asm volatile(
        "mma.sync.aligned.m16n8k16.row.col.f32.f16.f16.f32 "
        "{%0,%1,%2,%3}, {%4,%5,%6,%7}, {%8,%9}, {%0,%1,%2,%3};"
        : "+f"(c0), "+f"(c1), "+f"(c2), "+f"(c3)
        : "r"(a0), "r"(a1), "r"(a2), "r"(a3), "r"(b0), "r"(b1));
}

__device__ __forceinline__ void ldsm4(
    uint32_t& r0, uint32_t& r1, uint32_t& r2, uint32_t& r3, uint32_t addr)
{
    asm volatile(
        "ldmatrix.sync.aligned.m8n8.x4.shared.b16 {%0,%1,%2,%3}, [%4];"
        : "=r"(r0), "=r"(r1), "=r"(r2), "=r"(r3) : "r"(addr));
}
__device__ __forceinline__ void ldsm4t(
    uint32_t& r0, uint32_t& r1, uint32_t& r2, uint32_t& r3, uint32_t addr)
{
    asm volatile(
        "ldmatrix.sync.aligned.m8n8.x4.trans.shared.b16 {%0,%1,%2,%3}, [%4];"
        : "=r"(r0), "=r"(r1), "=r"(r2), "=r"(r3) : "r"(addr));
}

__device__ __forceinline__ void cp16(uint32_t saddr, const void* gptr) {
    asm volatile("cp.async.cg.shared.global [%0], [%1], 16;\n"
                 :: "r"(saddr), "l"(gptr));
}
__device__ __forceinline__ void cp_commit() {
    asm volatile("cp.async.commit_group;\n");
}
template<int N> __device__ __forceinline__ void cp_wait() {
    asm volatile("cp.async.wait_group %0;\n" :: "n"(N));
}

// ---------------------------------------------------------------------------
// Packing kernels — DEST-ORDER, vectorized stores.
// A-pack (unchanged layout): chunk c = ((mtile*KT16+kt)*32 + lane).
// W-pack (NEW, ldmatrix-ready): per (nb, kt): [hi(2)][row g(8)][8 k-halves]
//   = two contiguous 8x8 matrices of 128B each. One uint4 store per row.
// ---------------------------------------------------------------------------
__global__ void pack_a_kernel(const float* __restrict__ src,
                              __half* __restrict__ dst)
{
    int c = blockIdx.x * 256 + threadIdx.x;   // over MT*EMB/8 chunks
    int lane = c & 31;
    int kt   = (c >> 5) & (KT16 - 1);
    int mt   = c >> 11;
    int g = lane >> 2, tig = lane & 3;
    int m0 = mt * 16 + g;
    int k0 = kt * 16 + tig * 2;

    const float* r0 = src + (size_t)m0 * EMB + k0;
    const float* r1 = src + (size_t)(m0 + 8) * EMB + k0;
    float2 a00 = *(const float2*)(r0);
    float2 a01 = *(const float2*)(r0 + 8);
    float2 a10 = *(const float2*)(r1);
    float2 a11 = *(const float2*)(r1 + 8);

    uint4 out;
    out.x = h2u(a00.x, a00.y);
    out.y = h2u(a10.x, a10.y);
    out.z = h2u(a01.x, a01.y);
    out.w = h2u(a11.x, a11.y);
    *(uint4*)(dst + (size_t)c * 8) = out;
}

// Merged W pack: chunks [0, NQKV*128) -> Wqkv, [NQKV*128, ..) -> Wo.
// chunk c (within a matrix): g = c&7, hi = (c>>3)&1, kt = (c>>4)&63, nb = c>>10.
// Row = 8 contiguous k-halves of output row n = nb*8+g at k = kt*16+hi*8.
__global__ void pack_w_kernel(
    const float* __restrict__ Wq, const float* __restrict__ Wk,
    const float* __restrict__ Wv, const float* __restrict__ Wo,
    const float* __restrict__ bq, const float* __restrict__ bk,
    const float* __restrict__ bv,
    __half* __restrict__ Wqkvp, __half* __restrict__ Wop,
    float* __restrict__ bp)
{
    int c = blockIdx.x * 256 + threadIdx.x;   // over (NQKV+EMB)*EMB/8 chunks
    const int QKV_CHUNKS = NQKV * (EMB / 8);  // 393216
    int cl = (c < QKV_CHUNKS) ? c : c - QKV_CHUNKS;
    int g  = cl & 7;
    int hi = (cl >> 3) & 1;
    int kt = (cl >> 4) & (KT16 - 1);
    int nb = cl >> 10;
    int n  = nb * 8 + g;
    int k0 = kt * 16 + hi * 8;

    const float* W;
    float s;
    __half* dst;
    if (c < QKV_CHUNKS) {
        s = (n < 1024) ? (0.125f * LOG2E) : 1.0f;
        W = (n < 1024) ? Wq : (n < 2048) ? Wk : Wv;
        dst = Wqkvp;
    } else {
        s = 1.0f;
        W = Wo;
        dst = Wop;
    }
    const float* row = W + (size_t)(n & 1023) * 1024 + k0;
    float4 f0 = *(const float4*)(row);
    float4 f1 = *(const float4*)(row + 4);
    uint4 out;
    out.x = h2u(f0.x * s, f0.y * s);
    out.y = h2u(f0.z * s, f0.w * s);
    out.z = h2u(f1.x * s, f1.y * s);
    out.w = h2u(f1.z * s, f1.w * s);
    *(uint4*)(dst + (size_t)cl * 8) = out;

    if (c < NQKV) {
        const float* b = (c < 1024) ? bq : (c < 2048) ? bk : bv;
        bp[c] = ((c < 1024) ? (0.125f * LOG2E) : 1.0f) * b[c & 1023];
    }
}

// ---------------------------------------------------------------------------
// fp16 GEMM (m16n8k16), templated on pipeline depth & occupancy.
// B fragments now via ldmatrix.x4: one instruction yields b0/b1 for TWO
// n-tiles (4 ldsm4 per ks instead of 8 LDS.64).
//   NS=3, OCC=2 (QKV, 5.2 waves); NS=2, OCC=3 (O-proj, 1.15 waves).
// ---------------------------------------------------------------------------
#define ASTGB 16384
#define WSTGB 16384
#define GEMM_ITERS (EMB/64)

template<int NS, int OCC>
__global__ __launch_bounds__(128, OCC) void gemm_tc(
    const __half* __restrict__ A,
    const __half* __restrict__ W,
    const float* __restrict__ bias,
    void* __restrict__ Cv, int ldc, int out_half)
{
    extern __shared__ __align__(16) char smem[];
    char* As = smem;                      // [NS][ASTGB]

    const int tid  = threadIdx.x;
    const int w    = tid >> 5;
    const int lane = tid & 31;
    const int g    = lane >> 2;
    const int tig  = lane & 3;
    const int wm   = w >> 1;
    const int wn   = w & 1;
    const int m0   = blockIdx.y * 128;
    const int n0   = blockIdx.x * 128;
    const int m0t  = m0 >> 4;
    const int n0b  = n0 >> 3;

    uint32_t asb = (uint32_t)__cvta_generic_to_shared(As);
    uint32_t wsb = asb + NS * ASTGB;

    // ldmatrix lane offset within a (nt-pair, ks) group:
    // group = lane>>3: 0,1 -> nt even (hi 0/1); 2,3 -> nt odd (hi 0/1)
    const uint32_t bl_nt = (uint32_t)(lane >> 4);          // +0 or +1 nt
    const uint32_t bl_hi = (uint32_t)((lane >> 3) & 1);    // hi
    const uint32_t bl_row = (uint32_t)(lane & 7);

    float acc[4][8][4];
#pragma unroll
    for (int mt = 0; mt < 4; mt++)
#pragma unroll
        for (int nt = 0; nt < 8; nt++)
#pragma unroll
            for (int j = 0; j < 4; j++) acc[mt][nt][j] = 0.0f;

    auto load_stage = [&](int st, int ktb) {
#pragma unroll
        for (int i = 0; i < 8; i++) {
            int idx = tid + i * 128;          // 0..1023 (16B chunks)
            int mt = idx >> 7, ra = idx & 127;
            int kta = ra >> 5, ca = ra & 31;
            cp16(asb + (uint32_t)(st * ASTGB + idx * 16),
                 A + ((size_t)(m0t + mt) * KT16 + ktb + kta) * 256 + ca * 8);
            int nb = idx >> 6, rw = idx & 63;
            int ktw = rw >> 4, cw = rw & 15;
            cp16(wsb + (uint32_t)(st * WSTGB + idx * 16),
                 W + ((size_t)(n0b + nb) * KT16 + ktb + ktw) * 128 + cw * 8);
        }
    };

#pragma unroll
    for (int s = 0; s < NS - 1; s++) {
        load_stage(s, s * 4);
        cp_commit();
    }

    for (int it = 0; it < GEMM_ITERS; it++) {
        const int st = it % NS;
        if (it + NS - 1 < GEMM_ITERS) cp_wait<NS - 2>(); else cp_wait<0>();
        __syncthreads();

        if (it + NS - 1 < GEMM_ITERS) {
            load_stage((it + NS - 1) % NS, (it + NS - 1) * 4);
            cp_commit();
        }

        const char* as = As + st * ASTGB;
        const uint32_t ws = wsb + st * WSTGB;
#pragma unroll
        for (int ks = 0; ks < 4; ks++) {
            uint4 a4[4];
#pragma unroll
            for (int mt = 0; mt < 4; mt++)
                a4[mt] = *(const uint4*)(as + (((wm * 4 + mt) * 4 + ks) * 32
                                             + lane) * 16);
#pragma unroll
            for (int j = 0; j < 4; j++) {
                // nt pair (2j, 2j+1), both hi matrices, via one ldmatrix.x4
                uint32_t nb_l = (uint32_t)(wn * 8 + 2 * j) + bl_nt;
                uint32_t addr = ws + ((nb_l * 4 + ks) * 2 + bl_hi) * 128
                              + bl_row * 16;
                uint32_t b0, b1, b2, b3;
                ldsm4(b0, b1, b2, b3, addr);
#pragma unroll
                for (int mt = 0; mt < 4; mt++)
                    mma_f16(acc[mt][2*j][0], acc[mt][2*j][1],
                            acc[mt][2*j][2], acc[mt][2*j][3],
                            a4[mt].x, a4[mt].y, a4[mt].z, a4[mt].w,
                            b0, b1);
#pragma unroll
                for (int mt = 0; mt < 4; mt++)
                    mma_f16(acc[mt][2*j+1][0], acc[mt][2*j+1][1],
                            acc[mt][2*j+1][2], acc[mt][2*j+1][3],
                            a4[mt].x, a4[mt].y, a4[mt].z, a4[mt].w,
                            b2, b3);
            }
        }
    }

    // Epilogue with bias
#pragma unroll
    for (int mt = 0; mt < 4; mt++) {
#pragma unroll
        for (int nt = 0; nt < 8; nt++) {
            const int ng  = n0 + wn * 64 + nt * 8 + 2 * tig;
            const int row = m0 + wm * 64 + mt * 16 + g;
            float2 bv = *(const float2*)(bias + ng);
            float o00 = acc[mt][nt][0] + bv.x;
            float o01 = acc[mt][nt][1] + bv.y;
            float o10 = acc[mt][nt][2] + bv.x;
            float o11 = acc[mt][nt][3] + bv.y;
            if (out_half) {
                __half* C = (__half*)Cv;
                *(__half2*)(C + (size_t)row * ldc + ng) =
                    __floats2half2_rn(o00, o01);
                *(__half2*)(C + (size_t)(row + 8) * ldc + ng) =
                    __floats2half2_rn(o10, o11);
            } else {
                float* C = (float*)Cv;
                *(float2*)(C + (size_t)row * ldc + ng) = make_float2(o00, o01);
                *(float2*)(C + (size_t)(row + 8) * ldc + ng) = make_float2(o10, o11);
            }
        }
    }
}

// ---------------------------------------------------------------------------
// Flash attention, fp16 mma (R13/R15 form — measured at ~93% of the legacy
// HMMA ceiling; unchanged). Fused per-16-key-slice pipeline (QK -> ex2 ->
// PV + ones-mma). 128-key double-buffered tiles, 3 CTAs/SM.
// ---------------------------------------------------------------------------
#define KVSTR 72
#define KVROWB (KVSTR*2)
#define TILEB (128*KVROWB)          // 18432 B per 128-key tile
#define ATTN_SMEM (4*TILEB)         // K0,K1,V0,V1 = 73728 B
#define ONES16 0x3C003C00u

__global__ __launch_bounds__(128, 3) void attn_tc()
{
    extern __shared__ __align__(16) char sm[];

    const int tid  = threadIdx.x;
    const int w    = tid >> 5;
    const int lane = tid & 31;
    const int g    = lane >> 2;
    const int tig  = lane & 3;
    const int s0   = blockIdx.x * 128;
    const int h    = blockIdx.y;
    const int b    = blockIdx.z;
    const size_t baseQ = (size_t)b * SS * NQKV + (size_t)h * HD;
    const size_t baseK = baseQ + 1024;
    const size_t baseV = baseQ + 2048;
    const int mrow = w * 32;

    uint32_t smb = (uint32_t)__cvta_generic_to_shared(sm);
    const uint32_t ksb[2] = {smb, smb + TILEB};
    const uint32_t vsb[2] = {smb + 2 * TILEB, smb + 3 * TILEB};

    const uint32_t k_lane = (uint32_t)(((lane >> 4) * 8 + (lane & 7)) * KVROWB
                                       + ((lane >> 3) & 1) * 16);
    const uint32_t v_lane = (uint32_t)((((lane >> 3) & 1) * 8 + (lane & 7)) * KVROWB
                                       + (lane >> 4) * 16);

    // Q fragments (loop-invariant)
    uint32_t qa[2][4][4];
#pragma unroll
    for (int t = 0; t < 2; t++) {
        const __half* q0 = g_qkv + baseQ + (size_t)(s0 + mrow + t * 16 + g) * NQKV;
        const __half* q1 = g_qkv + baseQ + (size_t)(s0 + mrow + t * 16 + 8 + g) * NQKV;
#pragma unroll
        for (int kt = 0; kt < 4; kt++) {
            qa[t][kt][0] = *(const uint32_t*)(q0 + kt * 16 + 2 * tig);
            qa[t][kt][1] = *(const uint32_t*)(q1 + kt * 16 + 2 * tig);
            qa[t][kt][2] = *(const uint32_t*)(q0 + kt * 16 + 2 * tig + 8);
            qa[t][kt][3] = *(const uint32_t*)(q1 + kt * 16 + 2 * tig + 8);
        }
    }

    auto load_tile = [&](int buf, int kt0) {
#pragma unroll
        for (int i = 0; i < 8; i++) {
            int idx = tid + i * 128;           // 0..1023
            int r = idx >> 3;                  // 0..127
            int c = idx & 7;
            cp16(ksb[buf] + (uint32_t)(r * KVROWB + c * 16),
                 g_qkv + baseK + (size_t)(kt0 + r) * NQKV + c * 8);
            cp16(vsb[buf] + (uint32_t)(r * KVROWB + c * 16),
                 g_qkv + baseV + (size_t)(kt0 + r) * NQKV + c * 8);
        }
    };

    load_tile(0, 0);
    cp_commit();

    float o[2][8][4];
#pragma unroll
    for (int t = 0; t < 2; t++)
#pragma unroll
        for (int nt = 0; nt < 8; nt++)
#pragma unroll
            for (int j = 0; j < 4; j++) o[t][nt][j] = 0.0f;
    float osum[2][4] = {{0,0,0,0},{0,0,0,0}};

    for (int kt0 = 0; kt0 < SS; kt0 += 128) {
        const int st = (kt0 >> 7) & 1;
        cp_wait<0>();
        __syncthreads();

        if (kt0 + 128 < SS) {
            load_tile(st ^ 1, kt0 + 128);
            cp_commit();
        }

        // fused per-16-key slice: QK -> ex2 -> PV (+row-sum mma)
#pragma unroll
        for (int np = 0; np < 8; np++) {
            float s[2][2][4];
#pragma unroll
            for (int t = 0; t < 2; t++)
#pragma unroll
                for (int p = 0; p < 2; p++)
#pragma unroll
                    for (int j = 0; j < 4; j++) s[t][p][j] = 0.0f;

#pragma unroll
            for (int kt = 0; kt < 4; kt++) {
                uint32_t b0, b1, b2, b3;
                ldsm4(b0, b1, b2, b3,
                      ksb[st] + (uint32_t)(np * 16 * KVROWB + kt * 32) + k_lane);
                mma_f16(s[0][0][0], s[0][0][1], s[0][0][2], s[0][0][3],
                        qa[0][kt][0], qa[0][kt][1], qa[0][kt][2], qa[0][kt][3],
                        b0, b1);
                mma_f16(s[1][0][0], s[1][0][1], s[1][0][2], s[1][0][3],
                        qa[1][kt][0], qa[1][kt][1], qa[1][kt][2], qa[1][kt][3],
                        b0, b1);
                mma_f16(s[0][1][0], s[0][1][1], s[0][1][2], s[0][1][3],
                        qa[0][kt][0], qa[0][kt][1], qa[0][kt][2], qa[0][kt][3],
                        b2, b3);
                mma_f16(s[1][1][0], s[1][1][1], s[1][1][2], s[1][1][3],
                        qa[1][kt][0], qa[1][kt][1], qa[1][kt][2], qa[1][kt][3],
                        b2, b3);
            }

            uint32_t pa[2][4];
#pragma unroll
            for (int t = 0; t < 2; t++) {
                pa[t][0] = ex2h2(h2u(s[t][0][0], s[t][0][1]));
                pa[t][1] = ex2h2(h2u(s[t][0][2], s[t][0][3]));
                pa[t][2] = ex2h2(h2u(s[t][1][0], s[t][1][1]));
                pa[t][3] = ex2h2(h2u(s[t][1][2], s[t][1][3]));
                mma_f16(osum[t][0], osum[t][1], osum[t][2], osum[t][3],
                        pa[t][0], pa[t][1], pa[t][2], pa[t][3],
                        ONES16, ONES16);
            }

#pragma unroll
            for (int nbp = 0; nbp < 4; nbp++) {
                uint32_t b0, b1, b2, b3;
                ldsm4t(b0, b1, b2, b3,
                       vsb[st] + (uint32_t)(np * 16 * KVROWB + nbp * 32) + v_lane);
                mma_f16(o[0][2*nbp][0], o[0][2*nbp][1], o[0][2*nbp][2], o[0][2*nbp][3],
                        pa[0][0], pa[0][1], pa[0][2], pa[0][3], b0, b1);
                mma_f16(o[1][2*nbp][0], o[1][2*nbp][1], o[1][2*nbp][2], o[1][2*nbp][3],
                        pa[1][0], pa[1][1], pa[1][2], pa[1][3], b0, b1);
                mma_f16(o[0][2*nbp+1][0], o[0][2*nbp+1][1], o[0][2*nbp+1][2], o[0][2*nbp+1][3],
                        pa[0][0], pa[0][1], pa[0][2], pa[0][3], b2, b3);
                mma_f16(o[1][2*nbp+1][0], o[1][2*nbp+1][1], o[1][2*nbp+1][2], o[1][2*nbp+1][3],
                        pa[1][0], pa[1][1], pa[1][2], pa[1][3], b2, b3);
            }
        }
    }

    // Normalize (row sums in osum: c0 = row g, c2 = row g+8), write O packed
#pragma unroll
    for (int t = 0; t < 2; t++) {
        const float inv0 = 1.0f / osum[t][0];
        const float inv1 = 1.0f / osum[t][2];
        const int m = b * SS + s0 + mrow + t * 16 + g;
        const size_t mtile = (size_t)(m >> 4);
#pragma unroll
        for (int nt = 0; nt < 8; nt++) {
            size_t hidx = ((mtile * KT16 + h * 4 + (nt >> 1)) * 32
                           + g * 4 + tig) * 8 + (nt & 1) * 4;
            uint2 val;
            val.x = h2u(o[t][nt][0] * inv0, o[t][nt][1] * inv0);
            val.y = h2u(o[t][nt][2] * inv1, o[t][nt][3] * inv1);
            *(uint2*)(g_o + hidx) = val;
        }
    }
}

// ---------------------------------------------------------------------------
extern "C" void kernel_launch(void* const* d_in, const int* in_sizes, int n_in,
                              void* d_out, int out_size)
{
    const float* x  = (const float*)d_in[0];
    const float* Wq = (const float*)d_in[1];
    const float* bq = (const float*)d_in[2];
    const float* Wk = (const float*)d_in[3];
    const float* bk = (const float*)d_in[4];
    const float* Wv = (const float*)d_in[5];
    const float* bv = (const float*)d_in[6];
    const float* Wo = (const float*)d_in[7];
    const float* bo = (const float*)d_in[8];

    __half *gx, *qkv, *o, *wqkv, *wo;
    float *bqkv;
    cudaGetSymbolAddress((void**)&gx,   g_x);
    cudaGetSymbolAddress((void**)&qkv,  g_qkv);
    cudaGetSymbolAddress((void**)&o,    g_o);
    cudaGetSymbolAddress((void**)&wqkv, g_wqkv);
    cudaGetSymbolAddress((void**)&bqkv, g_bqkv);
    cudaGetSymbolAddress((void**)&wo,   g_wo);

    const int SM3 = 3 * (ASTGB + WSTGB);   // 98304
    const int SM2 = 2 * (ASTGB + WSTGB);   // 65536
    cudaFuncSetAttribute(gemm_tc<3,2>,
                         cudaFuncAttributeMaxDynamicSharedMemorySize, SM3);
    cudaFuncSetAttribute(gemm_tc<2,3>,
                         cudaFuncAttributeMaxDynamicSharedMemorySize, SM2);
    cudaFuncSetAttribute(attn_tc,
                         cudaFuncAttributeMaxDynamicSharedMemorySize, ATTN_SMEM);

    // Dest-order vectorized packs (W pack merged: QKV + Wo in one launch)
    pack_a_kernel<<<(MT * EMB / 8) / 256, 256>>>(x, gx);
    pack_w_kernel<<<((NQKV + EMB) * EMB / 8) / 256, 256>>>(
        Wq, Wk, Wv, Wo, bq, bk, bv, wqkv, wo, bqkv);

    // Fused QKV projection: [8192 x 3072], fp16 out — 3-stage, 2 CTA/SM
    gemm_tc<3,2><<<dim3(NQKV / 128, MT / 128), 128, SM3>>>(
        gx, wqkv, bqkv, qkv, NQKV, 1);

    attn_tc<<<dim3(SS / 128, NH, BB), 128, ATTN_SMEM>>>();

    // Output projection: fp32 out — 2-stage, 3 CTA/SM (tail-wave friendly)
    gemm_tc<2,3><<<dim3(EMB / 128, MT / 128), 128, SM2>>>(
        o, wo, bo, d_out, EMB, 0);
}

// round 17
// speedup vs baseline: 1.0163x; 1.0163x over previous
#include <cuda_runtime.h>
#include <cuda_fp16.h>
#include <math.h>
#include <stdint.h>

#define EMB 1024
#define NH  16
#define HD  64
#define BB  4
#define SS  2048
#define MT  (BB*SS)    // 8192 rows
#define NQKV 3072
#define KT16 (EMB/16)  // 64 k16-tiles per 1024

// Scratch (allocation-free rule: __device__ globals)
__device__ __half g_x[(size_t)MT*EMB];
__device__ __half g_qkv[(size_t)MT*NQKV];
__device__ __half g_o[(size_t)MT*EMB];
__device__ __half g_wqkv[(size_t)NQKV*EMB];
__device__ float  g_bqkv[NQKV];
__device__ __half g_wo[(size_t)EMB*EMB];

#define LOG2E 1.44269504088896f

__device__ __forceinline__ uint32_t h2u(float lo, float hi) {
    __half2 h = __floats2half2_rn(lo, hi);
    return *(uint32_t*)&h;
}
__device__ __forceinline__ uint32_t ex2h2(uint32_t x) {
    uint32_t r;
    asm("ex2.approx.f16x2 %0, %1;" : "=r"(r) : "r"(x));
    return r;
}

__device__ __forceinline__ void mma_f16(
    float& c0, float& c1, float& c2, float& c3,
    uint32_t a0, uint32_t a1, uint32_t a2, uint32_t a3,
    uint32_t b0, uint32_t b1)
{
    asm volatile(
        "mma.sync.aligned.m16n8k16.row.col.f32.f16.f16.f32 "
        "{%0,%1,%2,%3}, {%4,%5,%6,%7}, {%8,%9}, {%0,%1,%2,%3};"
        : "+f"(c0), "+f"(c1), "+f"(c2), "+f"(c3)
        : "r"(a0), "r"(a1), "r"(a2), "r"(a3), "r"(b0), "r"(b1));
}

__device__ __forceinline__ void ldsm4(
    uint32_t& r0, uint32_t& r1, uint32_t& r2, uint32_t& r3, uint32_t addr)
{
    asm volatile(
        "ldmatrix.sync.aligned.m8n8.x4.shared.b16 {%0,%1,%2,%3}, [%4];"
        : "=r"(r0), "=r"(r1), "=r"(r2), "=r"(r3) : "r"(addr));
}
__device__ __forceinline__ void ldsm4t(
    uint32_t& r0, uint32_t& r1, uint32_t& r2, uint32_t& r3, uint32_t addr)
{
    asm volatile(
        "ldmatrix.sync.aligned.m8n8.x4.trans.shared.b16 {%0,%1,%2,%3}, [%4];"
        : "=r"(r0), "=r"(r1), "=r"(r2), "=r"(r3) : "r"(addr));
}

__device__ __forceinline__ void cp16(uint32_t saddr, const void* gptr) {
    asm volatile("cp.async.cg.shared.global [%0], [%1], 16;\n"
                 :: "r"(saddr), "l"(gptr));
}
__device__ __forceinline__ void cp_commit() {
    asm volatile("cp.async.commit_group;\n");
}
template<int N> __device__ __forceinline__ void cp_wait() {
    asm volatile("cp.async.wait_group %0;\n" :: "n"(N));
}

// ---------------------------------------------------------------------------
// MERGED pack kernel — dest-order, vectorized stores, one launch.
//   blocks [0, A_BLKS):      x -> g_x       (A-pack, uint4 chunks)
//   blocks [A_BLKS, total):  Wq/Wk/Wv -> g_wqkv, Wo -> g_wo (uint2 chunks)
// A-pack layout: chunk c = ((mtile*KT16+kt)*32 + lane), 8 halves.
// W-pack layout: chunk c = ((nb*KT16+kt)*32 + lane), 4 halves.
// ---------------------------------------------------------------------------
#define A_CHUNKS   (MT * EMB / 8)            // 1048576
#define WQKV_CHUNKS (NQKV * EMB / 4)         // 786432
#define WO_CHUNKS  (EMB * EMB / 4)           // 262144
#define A_BLKS     (A_CHUNKS / 256)          // 4096
#define PACK_BLKS  (A_BLKS + (WQKV_CHUNKS + WO_CHUNKS) / 256)   // 8192

__global__ void pack_all_kernel(
    const float* __restrict__ x,
    const float* __restrict__ Wq, const float* __restrict__ Wk,
    const float* __restrict__ Wv, const float* __restrict__ Wo,
    const float* __restrict__ bq, const float* __restrict__ bk,
    const float* __restrict__ bv)
{
    int i = blockIdx.x * 256 + threadIdx.x;

    if (i < A_CHUNKS) {
        // ----- A-pack (x -> g_x) -----
        int c = i;
        int lane = c & 31;
        int kt   = (c >> 5) & (KT16 - 1);
        int mt   = c >> 11;
        int g = lane >> 2, tig = lane & 3;
        int m0 = mt * 16 + g;
        int k0 = kt * 16 + tig * 2;

        const float* r0 = x + (size_t)m0 * EMB + k0;
        const float* r1 = x + (size_t)(m0 + 8) * EMB + k0;
        float2 a00 = *(const float2*)(r0);
        float2 a01 = *(const float2*)(r0 + 8);
        float2 a10 = *(const float2*)(r1);
        float2 a11 = *(const float2*)(r1 + 8);

        uint4 out;
        out.x = h2u(a00.x, a00.y);
        out.y = h2u(a10.x, a10.y);
        out.z = h2u(a01.x, a01.y);
        out.w = h2u(a11.x, a11.y);
        *(uint4*)(g_x + (size_t)c * 8) = out;
        return;
    }

    int j = i - A_CHUNKS;
    if (j < WQKV_CHUNKS) {
        // ----- Wqkv pack (Q rows scaled by 1/8*log2(e)) -----
        int c = j;
        int lane = c & 31;
        int kt   = (c >> 5) & (KT16 - 1);
        int nb   = c >> 11;
        int g = lane >> 2, tig = lane & 3;
        int n = nb * 8 + g;
        float s = (n < 1024) ? (0.125f * LOG2E) : 1.0f;
        const float* W = (n < 1024) ? Wq : (n < 2048) ? Wk : Wv;
        const float* row = W + (size_t)(n & 1023) * 1024 + kt * 16 + tig * 2;
        float2 w0 = *(const float2*)(row);
        float2 w1 = *(const float2*)(row + 8);
        uint2 out;
        out.x = h2u(w0.x * s, w0.y * s);
        out.y = h2u(w1.x * s, w1.y * s);
        *(uint2*)(g_wqkv + (size_t)c * 4) = out;

        if (c < NQKV) {
            const float* b = (c < 1024) ? bq : (c < 2048) ? bk : bv;
            g_bqkv[c] = ((c < 1024) ? (0.125f * LOG2E) : 1.0f) * b[c & 1023];
        }
    } else {
        // ----- Wo pack -----
        int c = j - WQKV_CHUNKS;
        int lane = c & 31;
        int kt   = (c >> 5) & (KT16 - 1);
        int nb   = c >> 11;
        int g = lane >> 2, tig = lane & 3;
        const float* row = Wo + (size_t)(nb * 8 + g) * 1024 + kt * 16 + tig * 2;
        float2 w0 = *(const float2*)(row);
        float2 w1 = *(const float2*)(row + 8);
        uint2 out;
        out.x = h2u(w0.x, w0.y);
        out.y = h2u(w1.x, w1.y);
        *(uint2*)(g_wo + (size_t)c * 4) = out;
    }
}

// ---------------------------------------------------------------------------
// fp16 GEMM (m16n8k16), R15 measured-best form.
//   NS=3, OCC=2 (QKV); NS=2, OCC=3 (O-proj).
// CTA 128x128, BK=64, 128 thr = 4 warps (2x2), warp tile 64x64.
// ---------------------------------------------------------------------------
#define ASTGB 16384
#define WSTGB 16384
#define GEMM_ITERS (EMB/64)

template<int NS, int OCC>
__global__ __launch_bounds__(128, OCC) void gemm_tc(
    const __half* __restrict__ A,
    const __half* __restrict__ W,
    const float* __restrict__ bias,
    void* __restrict__ Cv, int ldc, int out_half)
{
    extern __shared__ __align__(16) char smem[];
    char* As = smem;                      // [NS][ASTGB]
    char* Ws = smem + NS * ASTGB;         // [NS][WSTGB]

    const int tid  = threadIdx.x;
    const int w    = tid >> 5;
    const int lane = tid & 31;
    const int g    = lane >> 2;
    const int tig  = lane & 3;
    const int wm   = w >> 1;
    const int wn   = w & 1;
    const int m0   = blockIdx.y * 128;
    const int n0   = blockIdx.x * 128;
    const int m0t  = m0 >> 4;
    const int n0b  = n0 >> 3;

    uint32_t asb = (uint32_t)__cvta_generic_to_shared(As);
    uint32_t wsb = (uint32_t)__cvta_generic_to_shared(Ws);

    float acc[4][8][4];
#pragma unroll
    for (int mt = 0; mt < 4; mt++)
#pragma unroll
        for (int nt = 0; nt < 8; nt++)
#pragma unroll
            for (int j = 0; j < 4; j++) acc[mt][nt][j] = 0.0f;

    auto load_stage = [&](int st, int ktb) {
#pragma unroll
        for (int i = 0; i < 8; i++) {
            int idx = tid + i * 128;          // 0..1023 (16B chunks)
            int mt = idx >> 7, ra = idx & 127;
            int kta = ra >> 5, ca = ra & 31;
            cp16(asb + (uint32_t)(st * ASTGB + idx * 16),
                 A + ((size_t)(m0t + mt) * KT16 + ktb + kta) * 256 + ca * 8);
            int nb = idx >> 6, rw = idx & 63;
            int ktw = rw >> 4, cw = rw & 15;
            cp16(wsb + (uint32_t)(st * WSTGB + idx * 16),
                 W + ((size_t)(n0b + nb) * KT16 + ktb + ktw) * 128 + cw * 8);
        }
    };

#pragma unroll
    for (int s = 0; s < NS - 1; s++) {
        load_stage(s, s * 4);
        cp_commit();
    }

    for (int it = 0; it < GEMM_ITERS; it++) {
        const int st = it % NS;
        if (it + NS - 1 < GEMM_ITERS) cp_wait<NS - 2>(); else cp_wait<0>();
        __syncthreads();

        if (it + NS - 1 < GEMM_ITERS) {
            load_stage((it + NS - 1) % NS, (it + NS - 1) * 4);
            cp_commit();
        }

        const char* as = As + st * ASTGB;
        const char* ws = Ws + st * WSTGB;
#pragma unroll
        for (int ks = 0; ks < 4; ks++) {
            uint4 a4[4];
#pragma unroll
            for (int mt = 0; mt < 4; mt++)
                a4[mt] = *(const uint4*)(as + (((wm * 4 + mt) * 4 + ks) * 32
                                             + lane) * 16);
#pragma unroll
            for (int nt = 0; nt < 8; nt++) {
                uint2 b2 = *(const uint2*)(ws + (((wn * 8 + nt) * 4 + ks) * 32
                                              + lane) * 8);
#pragma unroll
                for (int mt = 0; mt < 4; mt++)
                    mma_f16(acc[mt][nt][0], acc[mt][nt][1],
                            acc[mt][nt][2], acc[mt][nt][3],
                            a4[mt].x, a4[mt].y, a4[mt].z, a4[mt].w,
                            b2.x, b2.y);
            }
        }
    }

    // Epilogue with bias
#pragma unroll
    for (int mt = 0; mt < 4; mt++) {
#pragma unroll
        for (int nt = 0; nt < 8; nt++) {
            const int ng  = n0 + wn * 64 + nt * 8 + 2 * tig;
            const int row = m0 + wm * 64 + mt * 16 + g;
            float2 bv = *(const float2*)(bias + ng);
            float o00 = acc[mt][nt][0] + bv.x;
            float o01 = acc[mt][nt][1] + bv.y;
            float o10 = acc[mt][nt][2] + bv.x;
            float o11 = acc[mt][nt][3] + bv.y;
            if (out_half) {
                __half* C = (__half*)Cv;
                *(__half2*)(C + (size_t)row * ldc + ng) =
                    __floats2half2_rn(o00, o01);
                *(__half2*)(C + (size_t)(row + 8) * ldc + ng) =
                    __floats2half2_rn(o10, o11);
            } else {
                float* C = (float*)Cv;
                *(float2*)(C + (size_t)row * ldc + ng) = make_float2(o00, o01);
                *(float2*)(C + (size_t)(row + 8) * ldc + ng) = make_float2(o10, o11);
            }
        }
    }
}

// ---------------------------------------------------------------------------
// Flash attention, fp16 mma (R13/R15 form — ~77% tensor, near the legacy
// HMMA pipe ceiling; unchanged). Fused per-16-key-slice pipeline
// (QK -> ex2 -> PV + ones-mma). 128-key double-buffered tiles, 3 CTAs/SM.
// ---------------------------------------------------------------------------
#define KVSTR 72
#define KVROWB (KVSTR*2)
#define TILEB (128*KVROWB)          // 18432 B per 128-key tile
#define ATTN_SMEM (4*TILEB)         // K0,K1,V0,V1 = 73728 B
#define ONES16 0x3C003C00u

__global__ __launch_bounds__(128, 3) void attn_tc()
{
    extern __shared__ __align__(16) char sm[];

    const int tid  = threadIdx.x;
    const int w    = tid >> 5;
    const int lane = tid & 31;
    const int g    = lane >> 2;
    const int tig  = lane & 3;
    const int s0   = blockIdx.x * 128;
    const int h    = blockIdx.y;
    const int b    = blockIdx.z;
    const size_t baseQ = (size_t)b * SS * NQKV + (size_t)h * HD;
    const size_t baseK = baseQ + 1024;
    const size_t baseV = baseQ + 2048;
    const int mrow = w * 32;

    uint32_t smb = (uint32_t)__cvta_generic_to_shared(sm);
    const uint32_t ksb[2] = {smb, smb + TILEB};
    const uint32_t vsb[2] = {smb + 2 * TILEB, smb + 3 * TILEB};

    const uint32_t k_lane = (uint32_t)(((lane >> 4) * 8 + (lane & 7)) * KVROWB
                                       + ((lane >> 3) & 1) * 16);
    const uint32_t v_lane = (uint32_t)((((lane >> 3) & 1) * 8 + (lane & 7)) * KVROWB
                                       + (lane >> 4) * 16);

    // Q fragments (loop-invariant)
    uint32_t qa[2][4][4];
#pragma unroll
    for (int t = 0; t < 2; t++) {
        const __half* q0 = g_qkv + baseQ + (size_t)(s0 + mrow + t * 16 + g) * NQKV;
        const __half* q1 = g_qkv + baseQ + (size_t)(s0 + mrow + t * 16 + 8 + g) * NQKV;
#pragma unroll
        for (int kt = 0; kt < 4; kt++) {
            qa[t][kt][0] = *(const uint32_t*)(q0 + kt * 16 + 2 * tig);
            qa[t][kt][1] = *(const uint32_t*)(q1 + kt * 16 + 2 * tig);
            qa[t][kt][2] = *(const uint32_t*)(q0 + kt * 16 + 2 * tig + 8);
            qa[t][kt][3] = *(const uint32_t*)(q1 + kt * 16 + 2 * tig + 8);
        }
    }

    auto load_tile = [&](int buf, int kt0) {
#pragma unroll
        for (int i = 0; i < 8; i++) {
            int idx = tid + i * 128;           // 0..1023
            int r = idx >> 3;                  // 0..127
            int c = idx & 7;
            cp16(ksb[buf] + (uint32_t)(r * KVROWB + c * 16),
                 g_qkv + baseK + (size_t)(kt0 + r) * NQKV + c * 8);
            cp16(vsb[buf] + (uint32_t)(r * KVROWB + c * 16),
                 g_qkv + baseV + (size_t)(kt0 + r) * NQKV + c * 8);
        }
    };

    load_tile(0, 0);
    cp_commit();

    float o[2][8][4];
#pragma unroll
    for (int t = 0; t < 2; t++)
#pragma unroll
        for (int nt = 0; nt < 8; nt++)
#pragma unroll
            for (int j = 0; j < 4; j++) o[t][nt][j] = 0.0f;
    float osum[2][4] = {{0,0,0,0},{0,0,0,0}};

    for (int kt0 = 0; kt0 < SS; kt0 += 128) {
        const int st = (kt0 >> 7) & 1;
        cp_wait<0>();
        __syncthreads();

        if (kt0 + 128 < SS) {
            load_tile(st ^ 1, kt0 + 128);
            cp_commit();
        }

        // fused per-16-key slice: QK -> ex2 -> PV (+row-sum mma)
#pragma unroll
        for (int np = 0; np < 8; np++) {
            float s[2][2][4];
#pragma unroll
            for (int t = 0; t < 2; t++)
#pragma unroll
                for (int p = 0; p < 2; p++)
#pragma unroll
                    for (int j = 0; j < 4; j++) s[t][p][j] = 0.0f;

#pragma unroll
            for (int kt = 0; kt < 4; kt++) {
                uint32_t b0, b1, b2, b3;
                ldsm4(b0, b1, b2, b3,
                      ksb[st] + (uint32_t)(np * 16 * KVROWB + kt * 32) + k_lane);
                mma_f16(s[0][0][0], s[0][0][1], s[0][0][2], s[0][0][3],
                        qa[0][kt][0], qa[0][kt][1], qa[0][kt][2], qa[0][kt][3],
                        b0, b1);
                mma_f16(s[1][0][0], s[1][0][1], s[1][0][2], s[1][0][3],
                        qa[1][kt][0], qa[1][kt][1], qa[1][kt][2], qa[1][kt][3],
                        b0, b1);
                mma_f16(s[0][1][0], s[0][1][1], s[0][1][2], s[0][1][3],
                        qa[0][kt][0], qa[0][kt][1], qa[0][kt][2], qa[0][kt][3],
                        b2, b3);
                mma_f16(s[1][1][0], s[1][1][1], s[1][1][2], s[1][1][3],
                        qa[1][kt][0], qa[1][kt][1], qa[1][kt][2], qa[1][kt][3],
                        b2, b3);
            }

            uint32_t pa[2][4];
#pragma unroll
            for (int t = 0; t < 2; t++) {
                pa[t][0] = ex2h2(h2u(s[t][0][0], s[t][0][1]));
                pa[t][1] = ex2h2(h2u(s[t][0][2], s[t][0][3]));
                pa[t][2] = ex2h2(h2u(s[t][1][0], s[t][1][1]));
                pa[t][3] = ex2h2(h2u(s[t][1][2], s[t][1][3]));
                mma_f16(osum[t][0], osum[t][1], osum[t][2], osum[t][3],
                        pa[t][0], pa[t][1], pa[t][2], pa[t][3],
                        ONES16, ONES16);
            }

#pragma unroll
            for (int nbp = 0; nbp < 4; nbp++) {
                uint32_t b0, b1, b2, b3;
                ldsm4t(b0, b1, b2, b3,
                       vsb[st] + (uint32_t)(np * 16 * KVROWB + nbp * 32) + v_lane);
                mma_f16(o[0][2*nbp][0], o[0][2*nbp][1], o[0][2*nbp][2], o[0][2*nbp][3],
                        pa[0][0], pa[0][1], pa[0][2], pa[0][3], b0, b1);
                mma_f16(o[1][2*nbp][0], o[1][2*nbp][1], o[1][2*nbp][2], o[1][2*nbp][3],
                        pa[1][0], pa[1][1], pa[1][2], pa[1][3], b0, b1);
                mma_f16(o[0][2*nbp+1][0], o[0][2*nbp+1][1], o[0][2*nbp+1][2], o[0][2*nbp+1][3],
                        pa[0][0], pa[0][1], pa[0][2], pa[0][3], b2, b3);
                mma_f16(o[1][2*nbp+1][0], o[1][2*nbp+1][1], o[1][2*nbp+1][2], o[1][2*nbp+1][3],
                        pa[1][0], pa[1][1], pa[1][2], pa[1][3], b2, b3);
            }
        }
    }

    // Normalize (row sums in osum: c0 = row g, c2 = row g+8), write O packed
#pragma unroll
    for (int t = 0; t < 2; t++) {
        const float inv0 = 1.0f / osum[t][0];
        const float inv1 = 1.0f / osum[t][2];
        const int m = b * SS + s0 + mrow + t * 16 + g;
        const size_t mtile = (size_t)(m >> 4);
#pragma unroll
        for (int nt = 0; nt < 8; nt++) {
            size_t hidx = ((mtile * KT16 + h * 4 + (nt >> 1)) * 32
                           + g * 4 + tig) * 8 + (nt & 1) * 4;
            uint2 val;
            val.x = h2u(o[t][nt][0] * inv0, o[t][nt][1] * inv0);
            val.y = h2u(o[t][nt][2] * inv1, o[t][nt][3] * inv1);
            *(uint2*)(g_o + hidx) = val;
        }
    }
}

// ---------------------------------------------------------------------------
extern "C" void kernel_launch(void* const* d_in, const int* in_sizes, int n_in,
                              void* d_out, int out_size)
{
    const float* x  = (const float*)d_in[0];
    const float* Wq = (const float*)d_in[1];
    const float* bq = (const float*)d_in[2];
    const float* Wk = (const float*)d_in[3];
    const float* bk = (const float*)d_in[4];
    const float* Wv = (const float*)d_in[5];
    const float* bv = (const float*)d_in[6];
    const float* Wo = (const float*)d_in[7];
    const float* bo = (const float*)d_in[8];

    __half *gx, *qkv, *o, *wqkv, *wo;
    float *bqkv;
    cudaGetSymbolAddress((void**)&gx,   g_x);
    cudaGetSymbolAddress((void**)&qkv,  g_qkv);
    cudaGetSymbolAddress((void**)&o,    g_o);
    cudaGetSymbolAddress((void**)&wqkv, g_wqkv);
    cudaGetSymbolAddress((void**)&bqkv, g_bqkv);
    cudaGetSymbolAddress((void**)&wo,   g_wo);

    const int SM3 = 3 * (ASTGB + WSTGB);   // 98304
    const int SM2 = 2 * (ASTGB + WSTGB);   // 65536
    cudaFuncSetAttribute(gemm_tc<3,2>,
                         cudaFuncAttributeMaxDynamicSharedMemorySize, SM3);
    cudaFuncSetAttribute(gemm_tc<2,3>,
                         cudaFuncAttributeMaxDynamicSharedMemorySize, SM2);
    cudaFuncSetAttribute(attn_tc,
                         cudaFuncAttributeMaxDynamicSharedMemorySize, ATTN_SMEM);

    // Single merged preprocessing launch (x + all weights + biases)
    pack_all_kernel<<<PACK_BLKS, 256>>>(x, Wq, Wk, Wv, Wo, bq, bk, bv);

    // Fused QKV projection: [8192 x 3072], fp16 out — 3-stage, 2 CTA/SM
    gemm_tc<3,2><<<dim3(NQKV / 128, MT / 128), 128, SM3>>>(
        gx, wqkv, bqkv, qkv, NQKV, 1);

    attn_tc<<<dim3(SS / 128, NH, BB), 128, ATTN_SMEM>>>();

    // Output projection: fp32 out — 2-stage, 3 CTA/SM
    gemm_tc<2,3><<<dim3(EMB / 128, MT / 128), 128, SM2>>>(
        o, wo, bo, d_out, EMB, 0);
}